// round 1
// baseline (speedup 1.0000x reference)
#include <cuda_runtime.h>
#include <cstddef>

// Problem: ghost-cell padding with affine boundary conditions.
// arr:       (F=4, NX=4096, NY=4096) float32
// bc_const:  (2, 2) float32, indexed [axis, side]
// bc_factor: (2, 2) float32, indexed [axis, side]
// out:       (F, NX+2, NY+2) float32
//
// out[f, 1:-1, 1:-1] = arr[f]
// out[f,  0, 1:-1]   = bc_const[0,0] + bc_factor[0,0] * arr[f,  0, :]
// out[f, -1, 1:-1]   = bc_const[0,1] + bc_factor[0,1] * arr[f, -1, :]
// out[f, 1:-1,  0]   = bc_const[1,0] + bc_factor[1,0] * arr[f, :,  0]
// out[f, 1:-1, -1]   = bc_const[1,1] + bc_factor[1,1] * arr[f, :, -1]
// corners = 0

static constexpr int F  = 4;
static constexpr int NX = 4096;
static constexpr int NY = 4096;
static constexpr int PX = NX + 2;   // 4098
static constexpr int PY = NY + 2;   // 4098

static constexpr int THREADS = 256;

__global__ void __launch_bounds__(THREADS)
ghost_pad_kernel(const float* __restrict__ arr,
                 const float* __restrict__ bc_const,
                 const float* __restrict__ bc_factor,
                 float* __restrict__ out)
{
    const int row = blockIdx.x;        // 0 .. PX-1 (padded row index)
    const int f   = blockIdx.y;        // field index

    float* __restrict__ orow = out + ((size_t)f * PX + row) * PY;

    if (row == 0) {
        // Top ghost row: affine of arr[f, 0, :]; corners = 0.
        const float* __restrict__ a = arr + (size_t)f * NX * NY;  // row 0
        const float c   = bc_const[0 * 2 + 0];
        const float fac = bc_factor[0 * 2 + 0];
        for (int j = threadIdx.x; j < PY; j += THREADS) {
            float v = (j == 0 || j == PY - 1) ? 0.0f : fmaf(fac, a[j - 1], c);
            orow[j] = v;
        }
    } else if (row == PX - 1) {
        // Bottom ghost row: affine of arr[f, NX-1, :]; corners = 0.
        const float* __restrict__ a = arr + ((size_t)f * NX + (NX - 1)) * NY;
        const float c   = bc_const[0 * 2 + 1];
        const float fac = bc_factor[0 * 2 + 1];
        for (int j = threadIdx.x; j < PY; j += THREADS) {
            float v = (j == 0 || j == PY - 1) ? 0.0f : fmaf(fac, a[j - 1], c);
            orow[j] = v;
        }
    } else {
        // Interior row: copy arr[f, row-1, :] shifted by 1; endpoints are
        // the axis-1 ghost columns.
        const float* __restrict__ a = arr + ((size_t)f * NX + (row - 1)) * NY;
        const float cl = bc_const[1 * 2 + 0];
        const float fl = bc_factor[1 * 2 + 0];
        const float cr = bc_const[1 * 2 + 1];
        const float fr = bc_factor[1 * 2 + 1];
        const float a0 = a[0];
        const float a1 = a[NY - 1];
        for (int j = threadIdx.x; j < PY; j += THREADS) {
            float v;
            if (j == 0)            v = fmaf(fl, a0, cl);
            else if (j == PY - 1)  v = fmaf(fr, a1, cr);
            else                   v = a[j - 1];
            orow[j] = v;
        }
    }
}

extern "C" void kernel_launch(void* const* d_in, const int* in_sizes, int n_in,
                              void* d_out, int out_size)
{
    const float* arr       = (const float*)d_in[0];
    const float* bc_const  = (const float*)d_in[1];
    const float* bc_factor = (const float*)d_in[2];
    float* out             = (float*)d_out;

    dim3 grid(PX, F);
    ghost_pad_kernel<<<grid, THREADS>>>(arr, bc_const, bc_factor, out);
}

// round 2
// speedup vs baseline: 1.6763x; 1.6763x over previous
#include <cuda_runtime.h>
#include <cstddef>

// Ghost-cell padding with affine boundary conditions.
// arr: (4, 4096, 4096) f32 -> out: (4, 4098, 4098) f32
//
// Unified row model: every padded row `row` is produced as
//   value(j) = fmaf(fac, a[j-1], c)   for j in [1, PY-2]
//   value(0) = edgeL, value(PY-1) = edgeR
// where for interior rows (fac,c) = (1,0) (exact copy) and edges are the
// axis-1 affine ghosts; for top/bottom rows (fac,c) = bc[axis0,side] and
// edges are the zero corners.

static constexpr int F  = 4;
static constexpr int NX = 4096;
static constexpr int NY = 4096;
static constexpr int PX = NX + 2;   // 4098
static constexpr int PY = NY + 2;   // 4098

static constexpr int THREADS = 512;
// Row = 4098 elements = 2049 float2 pairs.
// Loop covers pairs 0..2047 in exactly 4 iterations of 512 threads;
// tail pair 2048 (elements 4096,4097) is written by thread 0.

__global__ void __launch_bounds__(THREADS)
ghost_pad_kernel(const float* __restrict__ arr,
                 const float* __restrict__ bc,   // bc_const  flat [axis*2+side]
                 const float* __restrict__ bf,   // bc_factor flat [axis*2+side]
                 float* __restrict__ out)
{
    const int row = blockIdx.x;     // 0 .. PX-1
    const int f   = blockIdx.y;     // field

    const float* __restrict__ a;
    float fac, c, edgeL, edgeR;

    if (row == 0) {
        // top ghost row: affine of arr[f, 0, :], corners 0
        a = arr + (size_t)f * NX * NY;
        c = bc[0]; fac = bf[0];
        edgeL = 0.0f; edgeR = 0.0f;
    } else if (row == PX - 1) {
        // bottom ghost row: affine of arr[f, NX-1, :], corners 0
        a = arr + ((size_t)f * NX + (NX - 1)) * NY;
        c = bc[1]; fac = bf[1];
        edgeL = 0.0f; edgeR = 0.0f;
    } else {
        // interior row: exact copy of arr[f, row-1, :], affine column ghosts
        a = arr + ((size_t)f * NX + (row - 1)) * NY;
        c = 0.0f; fac = 1.0f;                    // fma(1,x,0) == x exactly
        edgeL = fmaf(bf[2], a[0],      bc[2]);
        edgeR = fmaf(bf[3], a[NY - 1], bc[3]);
    }

    // Row start offset = rowIdx * 4098 elements -> always even,
    // so float2 stores at even j are always 8B-aligned.
    float* __restrict__ orow = out + ((size_t)f * PX + row) * PY;

    const int t = threadIdx.x;

    // Iteration 0: pair p = t, j = 2t. Only place j==0 can occur.
    {
        const int j  = 2 * t;
        const float l0 = a[(j == 0) ? 0 : (j - 1)];
        const float l1 = a[j];
        float v0 = fmaf(fac, l0, c);
        const float v1 = fmaf(fac, l1, c);
        if (j == 0) v0 = edgeL;
        *reinterpret_cast<float2*>(orow + j) = make_float2(v0, v1);
    }

    // Iterations 1..3: pure copy/affine, branch-free.
    // j in [1024, 4094]; loads a[j-1], a[j] always in-bounds; no ghosts.
    #pragma unroll
    for (int i = 1; i < 4; i++) {
        const int j  = 2 * (t + i * THREADS);
        const float l0 = a[j - 1];
        const float l1 = a[j];
        *reinterpret_cast<float2*>(orow + j) =
            make_float2(fmaf(fac, l0, c), fmaf(fac, l1, c));
    }

    // Tail pair p = 2048: elements j = 4096 (interior) and 4097 (right ghost).
    if (t == 0) {
        const float v0 = fmaf(fac, a[NY - 1], c);
        *reinterpret_cast<float2*>(orow + (PY - 2)) = make_float2(v0, edgeR);
    }
}

extern "C" void kernel_launch(void* const* d_in, const int* in_sizes, int n_in,
                              void* d_out, int out_size)
{
    const float* arr       = (const float*)d_in[0];
    const float* bc_const  = (const float*)d_in[1];
    const float* bc_factor = (const float*)d_in[2];
    float* out             = (float*)d_out;

    dim3 grid(PX, F);
    ghost_pad_kernel<<<grid, THREADS>>>(arr, bc_const, bc_factor, out);
}